// round 1
// baseline (speedup 1.0000x reference)
#include <cuda_runtime.h>
#include <cuda_bf16.h>
#include <math.h>

#define BB    4
#define NN    1024
#define HID   64
#define HEADS 16
#define TABLE_N 8192
#define D_MAX 32.0f

// Precomputed bias-vs-distance table: TABLE_N rows x HEADS floats (512 KB, L2-resident).
__device__ float g_table[TABLE_N * HEADS];

// Kernel 1: build the 1-D lookup table. out_k(d) = sum_h silu(d*w1_h + b1_h) * w2[h][k] + b2_k
__global__ void build_table_kernel(const float* __restrict__ w1,
                                   const float* __restrict__ b1,
                                   const float* __restrict__ w2,
                                   const float* __restrict__ b2) {
    int idx = blockIdx.x * blockDim.x + threadIdx.x;
    if (idx >= TABLE_N) return;
    float d = (float)idx * (D_MAX / (float)(TABLE_N - 1));
    float acc[HEADS];
#pragma unroll
    for (int k = 0; k < HEADS; k++) acc[k] = b2[k];
    for (int h = 0; h < HID; h++) {
        float a = fmaf(d, w1[h], b1[h]);
        float s = a / (1.0f + expf(-a));   // silu, accurate exp (build cost is negligible)
#pragma unroll
        for (int k = 0; k < HEADS; k++) acc[k] = fmaf(s, w2[h * HEADS + k], acc[k]);
    }
#pragma unroll
    for (int k = 0; k < HEADS; k++) g_table[idx * HEADS + k] = acc[k];
}

// Kernel 2: per-pair distance -> table lerp -> 16 coalesced float4 stores.
// Block = one (b, i) row. 256 threads, each covers 4 consecutive j.
__global__ __launch_bounds__(256, 2)
void bias_kernel(const float* __restrict__ coords, float* __restrict__ out) {
    int blk = blockIdx.x;
    int b = blk >> 10;          // / NN
    int i = blk & (NN - 1);

    const float* cb = coords + (size_t)b * NN * 3;
    float cix = cb[i * 3 + 0];
    float ciy = cb[i * 3 + 1];
    float ciz = cb[i * 3 + 2];

    int t = threadIdx.x;
    // 4 consecutive j coords = 12 floats = 3 aligned float4 loads
    const float4* cb4 = (const float4*)cb;
    float4 p0 = cb4[t * 3 + 0];
    float4 p1 = cb4[t * 3 + 1];
    float4 p2 = cb4[t * 3 + 2];

    float jx[4] = {p0.x, p0.w, p1.z, p2.y};
    float jy[4] = {p0.y, p1.x, p1.w, p2.z};
    float jz[4] = {p0.z, p1.y, p2.x, p2.w};

    const float4* tab4 = (const float4*)g_table;
    const float scale = (float)(TABLE_N - 1) / D_MAX;

    float vv[HEADS][4];   // fully unrolled -> registers

#pragma unroll
    for (int jj = 0; jj < 4; jj++) {
        float dx = jx[jj] - cix;
        float dy = jy[jj] - ciy;
        float dz = jz[jj] - ciz;
        float sq = fmaf(dx, dx, fmaf(dy, dy, dz * dz));
        float dd = sqrtf(sq);                      // d(i,i) == 0 exactly, matches ref
        float tf = fminf(dd * scale, (float)(TABLE_N - 2));
        int   i0 = (int)tf;
        float fr = tf - (float)i0;
#pragma unroll
        for (int c = 0; c < 4; c++) {
            float4 a  = __ldg(tab4 + (size_t)i0 * 4 + c);
            float4 bq = __ldg(tab4 + (size_t)i0 * 4 + 4 + c);
            vv[c * 4 + 0][jj] = fmaf(fr, bq.x - a.x, a.x);
            vv[c * 4 + 1][jj] = fmaf(fr, bq.y - a.y, a.y);
            vv[c * 4 + 2][jj] = fmaf(fr, bq.z - a.z, a.z);
            vv[c * 4 + 3][jj] = fmaf(fr, bq.w - a.w, a.w);
        }
    }

    // out[b][k][i][j], j = 4t..4t+3 : one STG.128 per head, fully coalesced per warp
#pragma unroll
    for (int k = 0; k < HEADS; k++) {
        float4 o = make_float4(vv[k][0], vv[k][1], vv[k][2], vv[k][3]);
        size_t off = (((size_t)(b * HEADS + k) * NN + i) * NN) + 4 * t;
        *(float4*)(out + off) = o;
    }
}

extern "C" void kernel_launch(void* const* d_in, const int* in_sizes, int n_in,
                              void* d_out, int out_size) {
    const float* coords = (const float*)d_in[0];
    const float* w1     = (const float*)d_in[1];
    const float* b1     = (const float*)d_in[2];
    const float* w2     = (const float*)d_in[3];
    const float* b2     = (const float*)d_in[4];
    float* out = (float*)d_out;

    build_table_kernel<<<TABLE_N / 256, 256>>>(w1, b1, w2, b2);
    bias_kernel<<<BB * NN, 256>>>(coords, out);
}

// round 5
// speedup vs baseline: 1.4818x; 1.4818x over previous
#include <cuda_runtime.h>
#include <cuda_fp16.h>
#include <math.h>

#define BB    4
#define NN    1024
#define HID   64
#define HEADS 16
#define TABLE_N 2048
#define D_MAX 32.0f
#define NBLK  148          // persistent: one block per SM

// Chunk-major packed table: g_ptab4[c * TABLE_N + r] (c = head-chunk 0..3) holds,
// for heads 4c..4c+3, the half2 pair (f(d_r)[k], f(d_{r+1})[k]).
// Chunk-major => 16-byte row stride per sub-table => LDS bank spread (8 slots, ~2-way).
// 2048 rows x 4 chunks x 16 B = 128 KB.
__device__ uint4 g_ptab4[4 * TABLE_N];

__device__ __forceinline__ void eval_row(float d, const float* __restrict__ w1,
                                         const float* __restrict__ b1,
                                         const float* __restrict__ w2,
                                         const float* __restrict__ b2,
                                         float* acc) {
#pragma unroll
    for (int k = 0; k < HEADS; k++) acc[k] = b2[k];
    for (int h = 0; h < HID; h++) {
        float a = fmaf(d, w1[h], b1[h]);
        float s = a / (1.0f + __expf(-a));   // silu
#pragma unroll
        for (int k = 0; k < HEADS; k++) acc[k] = fmaf(s, w2[h * HEADS + k], acc[k]);
    }
}

// Kernel 1: build packed pair table (chunk-major).
__global__ void build_table_kernel(const float* __restrict__ w1,
                                   const float* __restrict__ b1,
                                   const float* __restrict__ w2,
                                   const float* __restrict__ b2) {
    int idx = blockIdx.x * blockDim.x + threadIdx.x;
    if (idx >= TABLE_N) return;
    const float step = D_MAX / (float)(TABLE_N - 1);
    float d0 = (float)idx * step;
    int idx1 = (idx + 1 < TABLE_N) ? idx + 1 : idx;
    float d1 = (float)idx1 * step;

    float a0[HEADS], a1[HEADS];
    eval_row(d0, w1, b1, w2, b2, a0);
    eval_row(d1, w1, b1, w2, b2, a1);

#pragma unroll
    for (int c = 0; c < 4; c++) {
        __half2 h0 = __floats2half2_rn(a0[c * 4 + 0], a1[c * 4 + 0]);
        __half2 h1 = __floats2half2_rn(a0[c * 4 + 1], a1[c * 4 + 1]);
        __half2 h2 = __floats2half2_rn(a0[c * 4 + 2], a1[c * 4 + 2]);
        __half2 h3 = __floats2half2_rn(a0[c * 4 + 3], a1[c * 4 + 3]);
        uint4 v;
        v.x = *(unsigned*)&h0; v.y = *(unsigned*)&h1;
        v.z = *(unsigned*)&h2; v.w = *(unsigned*)&h3;
        g_ptab4[c * TABLE_N + idx] = v;
    }
}

// Kernel 2: persistent blocks (1/SM). Stage table into smem once, then loop rows.
// Per row: 256 threads x 4 consecutive j -> distance -> smem lerp -> 16 coalesced STG.128.
__global__ __launch_bounds__(256)
void bias_kernel(const float* __restrict__ coords, float* __restrict__ out) {
    extern __shared__ uint4 stab[];   // 4 * TABLE_N uint4 = 128 KB

    // One-time cooperative stage: 128 KB global -> smem.
    for (int s = threadIdx.x; s < 4 * TABLE_N; s += 256)
        stab[s] = g_ptab4[s];
    __syncthreads();

    const int t = threadIdx.x;
    const float scale = (float)(TABLE_N - 1) / D_MAX;

    for (int row = blockIdx.x; row < BB * NN; row += NBLK) {
        int b = row >> 10;          // / NN
        int i = row & (NN - 1);

        const float* cb = coords + (size_t)b * NN * 3;
        float cix = cb[i * 3 + 0];
        float ciy = cb[i * 3 + 1];
        float ciz = cb[i * 3 + 2];

        // 4 consecutive j coords = 12 floats = 3 aligned float4 loads (L1-resident)
        const float4* cb4 = (const float4*)cb;
        float4 p0 = cb4[t * 3 + 0];
        float4 p1 = cb4[t * 3 + 1];
        float4 p2 = cb4[t * 3 + 2];

        float jx[4] = {p0.x, p0.w, p1.z, p2.y};
        float jy[4] = {p0.y, p1.x, p1.w, p2.z};
        float jz[4] = {p0.z, p1.y, p2.x, p2.w};

        float vv[HEADS][4];

#pragma unroll
        for (int jj = 0; jj < 4; jj++) {
            float dx = jx[jj] - cix;
            float dy = jy[jj] - ciy;
            float dz = jz[jj] - ciz;
            float sq = fmaf(dx, dx, fmaf(dy, dy, dz * dz));
            float dd = sqrtf(sq);                      // d(i,i) == 0 exactly
            float tf = fminf(dd * scale, (float)(TABLE_N - 2));
            int   i0 = (int)tf;
            float fr = tf - (float)i0;
#pragma unroll
            for (int c = 0; c < 4; c++) {
                uint4 raw = stab[c * TABLE_N + i0];
#pragma unroll
                for (int q = 0; q < 4; q++) {
                    unsigned w = (q == 0) ? raw.x : (q == 1) ? raw.y
                               : (q == 2) ? raw.z : raw.w;
                    float2 pr = __half22float2(*(const __half2*)&w); // (f_i, f_{i+1})
                    vv[c * 4 + q][jj] = fmaf(fr, pr.y - pr.x, pr.x);
                }
            }
        }

        // out[b][k][i][j], j = 4t..4t+3 : one STG.128 per head, fully coalesced
#pragma unroll
        for (int k = 0; k < HEADS; k++) {
            float4 o = make_float4(vv[k][0], vv[k][1], vv[k][2], vv[k][3]);
            size_t off = (((size_t)(b * HEADS + k) * NN + i) * NN) + 4 * t;
            *(float4*)(out + off) = o;
        }
    }
}

extern "C" void kernel_launch(void* const* d_in, const int* in_sizes, int n_in,
                              void* d_out, int out_size) {
    const float* coords = (const float*)d_in[0];
    const float* w1     = (const float*)d_in[1];
    const float* b1     = (const float*)d_in[2];
    const float* w2     = (const float*)d_in[3];
    const float* b2     = (const float*)d_in[4];
    float* out = (float*)d_out;

    static int smem_set = 0;
    if (!smem_set) {
        cudaFuncSetAttribute(bias_kernel,
                             cudaFuncAttributeMaxDynamicSharedMemorySize,
                             4 * TABLE_N * sizeof(uint4));
        smem_set = 1;
    }

    build_table_kernel<<<TABLE_N / 256, 256>>>(w1, b1, w2, b2);
    bias_kernel<<<NBLK, 256, 4 * TABLE_N * sizeof(uint4)>>>(coords, out);
}

// round 6
// speedup vs baseline: 2.2001x; 1.4848x over previous
#include <cuda_runtime.h>
#include <cuda_fp16.h>
#include <math.h>

#define BB    4
#define NN    1024
#define HID   64
#define HEADS 16
#define TABLE_N 2048
#define D_MAX 32.0f
#define NBLK  148          // persistent: one block per SM

// Raw fp32 table: g_raw[row * 4 + c] = float4 of heads 4c..4c+3 at distance d_row.
__device__ float4 g_raw[TABLE_N * 4];

// Kernel 1: warp-per-row table eval. Lanes split the HID loop (2 h each),
// then shfl-butterfly reduce the 16 head accumulators. Full-chip parallel.
__global__ __launch_bounds__(256)
void build_raw_kernel(const float* __restrict__ w1,
                      const float* __restrict__ b1,
                      const float* __restrict__ w2,
                      const float* __restrict__ b2) {
    int warp = (blockIdx.x * blockDim.x + threadIdx.x) >> 5;
    int lane = threadIdx.x & 31;
    if (warp >= TABLE_N) return;

    const float step = D_MAX / (float)(TABLE_N - 1);
    float d = (float)warp * step;

    float acc[HEADS];
#pragma unroll
    for (int k = 0; k < HEADS; k++) acc[k] = 0.0f;

#pragma unroll
    for (int hh = 0; hh < HID / 32; hh++) {
        int h = lane + hh * 32;
        float a = fmaf(d, w1[h], b1[h]);
        float s = a / (1.0f + __expf(-a));   // silu
#pragma unroll
        for (int k = 0; k < HEADS; k++)
            acc[k] = fmaf(s, w2[h * HEADS + k], acc[k]);
    }

    // butterfly reduce: every lane ends with the full sum
#pragma unroll
    for (int off = 16; off >= 1; off >>= 1) {
#pragma unroll
        for (int k = 0; k < HEADS; k++)
            acc[k] += __shfl_xor_sync(0xffffffffu, acc[k], off);
    }

    if (lane == 0) {
#pragma unroll
        for (int c = 0; c < 4; c++)
            g_raw[warp * 4 + c] = make_float4(acc[c * 4 + 0] + b2[c * 4 + 0],
                                              acc[c * 4 + 1] + b2[c * 4 + 1],
                                              acc[c * 4 + 2] + b2[c * 4 + 2],
                                              acc[c * 4 + 3] + b2[c * 4 + 3]);
    }
}

// Kernel 2: persistent blocks (1/SM, 512 threads). Stage+pack table into smem once
// (chunk-major fp16 pairs), then loop rows 2-at-a-time.
// Smem entry stab[c*TABLE_N + r] = uint4 of 4 half2: (f(d_r)[k], f(d_{r+1})[k]), k=4c..4c+3.
__global__ __launch_bounds__(512)
void bias_kernel(const float* __restrict__ coords, float* __restrict__ out) {
    extern __shared__ uint4 stab[];   // 4 * TABLE_N uint4 = 128 KB

    // One-time stage + fp16 pair-pack: 128 KB smem from 512 KB raw (L2-resident).
    for (int s = threadIdx.x; s < 4 * TABLE_N; s += 512) {
        int c = s >> 11;               // s / TABLE_N
        int r = s & (TABLE_N - 1);
        int r1 = (r + 1 < TABLE_N) ? r + 1 : r;
        float4 a = g_raw[r * 4 + c];
        float4 b = g_raw[r1 * 4 + c];
        __half2 h0 = __floats2half2_rn(a.x, b.x);
        __half2 h1 = __floats2half2_rn(a.y, b.y);
        __half2 h2 = __floats2half2_rn(a.z, b.z);
        __half2 h3 = __floats2half2_rn(a.w, b.w);
        uint4 v;
        v.x = *(unsigned*)&h0; v.y = *(unsigned*)&h1;
        v.z = *(unsigned*)&h2; v.w = *(unsigned*)&h3;
        stab[s] = v;
    }
    __syncthreads();

    const int grp = threadIdx.x >> 8;        // 0 or 1: which row of the pair
    const int tt  = threadIdx.x & 255;       // j-position within the row
    const float scale = (float)(TABLE_N - 1) / D_MAX;

    for (int row0 = blockIdx.x * 2; row0 < BB * NN; row0 += NBLK * 2) {
        int row = row0 + grp;
        if (row >= BB * NN) break;
        int b = row >> 10;          // / NN
        int i = row & (NN - 1);

        const float* cb = coords + (size_t)b * NN * 3;
        float cix = cb[i * 3 + 0];
        float ciy = cb[i * 3 + 1];
        float ciz = cb[i * 3 + 2];

        // 4 consecutive j coords = 12 floats = 3 aligned float4 loads (L1/L2-resident)
        const float4* cb4 = (const float4*)cb;
        float4 p0 = cb4[tt * 3 + 0];
        float4 p1 = cb4[tt * 3 + 1];
        float4 p2 = cb4[tt * 3 + 2];

        float jx[4] = {p0.x, p0.w, p1.z, p2.y};
        float jy[4] = {p0.y, p1.x, p1.w, p2.z};
        float jz[4] = {p0.z, p1.y, p2.x, p2.w};

        float vv[HEADS][4];

#pragma unroll
        for (int jj = 0; jj < 4; jj++) {
            float dx = jx[jj] - cix;
            float dy = jy[jj] - ciy;
            float dz = jz[jj] - ciz;
            float sq = fmaf(dx, dx, fmaf(dy, dy, dz * dz));
            float dd = sqrtf(sq);                      // d(i,i) == 0 exactly
            float tf = fminf(dd * scale, (float)(TABLE_N - 2));
            int   i0 = (int)tf;
            float fr = tf - (float)i0;
#pragma unroll
            for (int c = 0; c < 4; c++) {
                uint4 raw = stab[c * TABLE_N + i0];
#pragma unroll
                for (int q = 0; q < 4; q++) {
                    unsigned w = (q == 0) ? raw.x : (q == 1) ? raw.y
                               : (q == 2) ? raw.z : raw.w;
                    float2 pr = __half22float2(*(const __half2*)&w); // (f_i, f_{i+1})
                    vv[c * 4 + q][jj] = fmaf(fr, pr.y - pr.x, pr.x);
                }
            }
        }

        // out[b][k][i][j], j = 4tt..4tt+3 : one STG.128 per head, fully coalesced
#pragma unroll
        for (int k = 0; k < HEADS; k++) {
            float4 o = make_float4(vv[k][0], vv[k][1], vv[k][2], vv[k][3]);
            size_t off = (((size_t)(b * HEADS + k) * NN + i) * NN) + 4 * tt;
            *(float4*)(out + off) = o;
        }
    }
}

extern "C" void kernel_launch(void* const* d_in, const int* in_sizes, int n_in,
                              void* d_out, int out_size) {
    const float* coords = (const float*)d_in[0];
    const float* w1     = (const float*)d_in[1];
    const float* b1     = (const float*)d_in[2];
    const float* w2     = (const float*)d_in[3];
    const float* b2     = (const float*)d_in[4];
    float* out = (float*)d_out;

    static int smem_set = 0;
    if (!smem_set) {
        cudaFuncSetAttribute(bias_kernel,
                             cudaFuncAttributeMaxDynamicSharedMemorySize,
                             4 * TABLE_N * sizeof(uint4));
        smem_set = 1;
    }

    build_raw_kernel<<<TABLE_N * 32 / 256, 256>>>(w1, b1, w2, b2);
    bias_kernel<<<NBLK, 512, 4 * TABLE_N * sizeof(uint4)>>>(coords, out);
}